// round 15
// baseline (speedup 1.0000x reference)
#include <cuda_runtime.h>
#include <cuda_bf16.h>
#include <cstdint>
#include <cstddef>

// Problem constants: inputs [8192, 64], capacity = ceil(1.25*8192/64) = 160
#define S   8192
#define E   64
#define CAP 160
#define ROW (E * CAP)               // 10240 floats per token row
#define SEC ((size_t)S * ROW)       // 83,886,080 elements per [s,e,c] section

#define NSEL E                      // 64 select blocks (bids 0..63)
#define FILL_TOK 4                  // token-rows per fill block (both sections)
#define NFILL (S / FILL_TOK)        // 2048 fill blocks
#define TPB 1024

// -------- device scratch (allocation-free: __device__ globals) --------
__device__ uint8_t  g_expert[S];
__device__ float    g_prob[S];
__device__ unsigned g_rbits[S];
__device__ int      g_loc[S];       // capacity slot per token, -1 if dropped
__device__ int      g_bar;          // select-phase barrier (+reset ticket)
__device__ int      g_tok[S];       // per-token handoff flag (0 at rest)

// acq_rel exchange: release orders this thread/block's prior stores before the
// flag; acquire orders the winner's subsequent loads/stores after it.
// No MEMBAR drain (unlike __threadfence) — this is the point.
__device__ __forceinline__ int atom_exch_acqrel(int* p, int v)
{
    int r;
    asm volatile("atom.acq_rel.gpu.exch.b32 %0, [%1], %2;"
                 : "=r"(r) : "l"(p), "r"(v) : "memory");
    return r;
}

// ============================================================================
// Block-wide inclusive scan over 1024 ints. *tot = block total.
// ============================================================================
__device__ __forceinline__ int block_incl_scan_1024(int v, int* tot, int* warpsums)
{
    int lane = threadIdx.x & 31, w = threadIdx.x >> 5;
    int inc = v;
    #pragma unroll
    for (int o = 1; o < 32; o <<= 1) {
        int n = __shfl_up_sync(0xFFFFFFFFu, inc, o);
        if (lane >= o) inc += n;
    }
    if (lane == 31) warpsums[w] = inc;
    __syncthreads();
    if (w == 0) {
        int sv = warpsums[lane];
        #pragma unroll
        for (int o = 1; o < 32; o <<= 1) {
            int n = __shfl_up_sync(0xFFFFFFFFu, sv, o);
            if (lane >= o) sv += n;
        }
        warpsums[lane] = sv;
    }
    __syncthreads();
    int res = inc + (w ? warpsums[w - 1] : 0);
    *tot = warpsums[31];
    __syncthreads();
    return res;
}

// Scatter token t's nonzero (if kept) into both sections.
__device__ __forceinline__ void scatter_token(float* out, int t, int ex, int loc,
                                              float prob, int write_mask)
{
    if (loc >= 0) {
        size_t off = (size_t)t * ROW + (size_t)ex * CAP + loc;
        out[off] = prob;
        if (write_mask) out[SEC + off] = 1.0f;
    }
}

// ============================================================================
// Single fused kernel.
//   bid >= NSEL : zero slab (sync-free streaming) -> __syncthreads ->
//                 acq_rel exch on its 4 token flags; second toucher scatters.
//   bid <  NSEL : token phase (128 tokens) -> co-resident device barrier ->
//                 exact radix select + slot scan -> per-token: write g_loc,
//                 acq_rel exch; second toucher scatters. Then barrier reset
//                 via second ticket round (replay-deterministic).
// ============================================================================
__global__ void __launch_bounds__(TPB) router_fused_kernel(
    const float* __restrict__ inputs, const float* __restrict__ rand,
    float* __restrict__ out, int write_mask, long long counts_off)
{
    const int bid = blockIdx.x;
    const int tid = threadIdx.x;

    if (bid >= NSEL) {
        // ---------------- fill block: sync-free streaming zero ----------------
        int fid = bid - NSEL;                       // 0 .. NFILL-1
        float4* base  = (float4*)out + (size_t)fid * (FILL_TOK * ROW / 4);
        float4* mbase = base + (SEC / 4);
        const float4 z = make_float4(0.f, 0.f, 0.f, 0.f);
        #pragma unroll
        for (int i = 0; i < FILL_TOK * ROW / 4 / TPB; ++i)   // 10 iterations
            base[tid + TPB * i] = z;
        if (write_mask) {
            #pragma unroll
            for (int i = 0; i < FILL_TOK * ROW / 4 / TPB; ++i)
                mbase[tid + TPB * i] = z;
        }
        __syncthreads();   // block-level: zeros issued before handoff

        if (tid < FILL_TOK) {
            int t = fid * FILL_TOK + tid;
            int r = atom_exch_acqrel(&g_tok[t], 1);   // release: zeros before flag
            if (r != 0) {
                // select already touched: g_loc/g_prob/g_expert visible (acquire)
                scatter_token(out, t, (int)g_expert[t], g_loc[t], g_prob[t],
                              write_mask);
                *(volatile int*)&g_tok[t] = 0;        // replay-safe reset
            }
        }
        return;
    }

    // ------------------- token phase: 128 tokens per block -------------------
    {
        int w    = tid >> 5;
        int lane = tid & 31;
        #pragma unroll
        for (int i = 0; i < 4; ++i) {
            int t = bid * 128 + i * 32 + w;
            float2 v = ((const float2*)(inputs + (size_t)t * E))[lane];
            float m;  int mi;
            if (v.x >= v.y) { m = v.x; mi = 2 * lane; } else { m = v.y; mi = 2 * lane + 1; }
            #pragma unroll
            for (int o = 16; o > 0; o >>= 1) {
                float om  = __shfl_xor_sync(0xFFFFFFFFu, m, o);
                int   omi = __shfl_xor_sync(0xFFFFFFFFu, mi, o);
                if (om > m || (om == m && omi < mi)) { m = om; mi = omi; }
            }
            float s = expf(v.x - m) + expf(v.y - m);
            #pragma unroll
            for (int o = 16; o > 0; o >>= 1)
                s += __shfl_xor_sync(0xFFFFFFFFu, s, o);
            if (lane == 0) {
                g_expert[t] = (uint8_t)mi;
                g_prob[t]   = 1.0f / s;
                g_rbits[t]  = __float_as_uint(rand[(size_t)t * E + mi]);
            }
        }
    }
    // barrier among the 64 select blocks (bids 0..63: all wave-1 co-resident)
    __threadfence();
    __syncthreads();
    if (tid == 0) {
        atomicAdd(&g_bar, 1);
        while (*(volatile int*)&g_bar < NSEL) __nanosleep(64);
    }
    __syncthreads();
    __threadfence();

    // ------------------- radix select + slot scan (expert = bid) -------------
    const int e = bid;
    __shared__ unsigned hist[256];
    __shared__ int s_warpsums[32];
    __shared__ unsigned s_prefix;
    __shared__ int s_k, s_total, s_done_sh;

    if (tid == 0) { s_prefix = 0; s_k = CAP; s_total = 0; s_done_sh = 0; }

    for (int pass = 3; pass >= 0; --pass) {
        __syncthreads();
        if (s_done_sh) break;
        if (tid < 256) hist[tid] = 0;
        __syncthreads();

        unsigned prefix = s_prefix;
        unsigned himask = (pass == 3) ? 0u : (0xFFFFFFFFu << ((pass + 1) * 8));
        int shift = pass * 8;

        #pragma unroll
        for (int c = 0; c < S / TPB; ++c) {
            int t = c * TPB + tid;
            if (g_expert[t] == (uint8_t)e) {
                unsigned b = g_rbits[t];
                if ((b & himask) == (prefix & himask))
                    atomicAdd(&hist[(b >> shift) & 255u], 1u);
            }
        }
        __syncthreads();

        int hv = (tid < 256) ? (int)hist[255 - tid] : 0;
        int tot;
        int suf = block_incl_scan_1024(hv, &tot, s_warpsums);

        int k = s_k;
        __syncthreads();

        if (tid < 256) {
            int i = 255 - tid;
            int above = suf - hv;
            if (pass == 3 && tid == 255) {
                s_total = suf;
                if (suf <= CAP) s_done_sh = 1;
            }
            if (suf >= k && above < k) {
                s_k = k - above;
                s_prefix = prefix | ((unsigned)i << shift);
            }
        }
    }
    __syncthreads();

    const int keep_all = (s_total <= CAP);
    const unsigned T   = s_prefix;
    const int need_eq  = keep_all ? 0 : s_k;
    const int total    = s_total;

    int runEq = 0, runGt = 0;
    #pragma unroll
    for (int c = 0; c < S / TPB; ++c) {
        int t = c * TPB + tid;
        bool assigned = (g_expert[t] == (uint8_t)e);
        unsigned b = assigned ? g_rbits[t] : 0u;
        int gtf, eqf;
        if (keep_all) { gtf = assigned ? 1 : 0; eqf = 0; }
        else {
            gtf = (assigned && b >  T) ? 1 : 0;
            eqf = (assigned && b == T) ? 1 : 0;
        }
        int packed = eqf | (gtf << 16);

        int tot;
        int incl = block_incl_scan_1024(packed, &tot, s_warpsums);
        int excl = incl - packed;
        int eq_excl = runEq + (excl & 0xFFFF);
        int gt_excl = runGt + (excl >> 16);

        if (assigned) {
            int kept = gtf || (eqf && eq_excl < need_eq);
            int loc  = kept ? (gt_excl + min(eq_excl, need_eq)) : -1;
            g_loc[t] = loc;
            // handoff: release my g_loc write; if fill already zeroed this
            // slab (r != 0), its zeros are visible (acquire) -> scatter here.
            int r = atom_exch_acqrel(&g_tok[t], 2);
            if (r != 0) {
                scatter_token(out, t, e, loc, g_prob[t], write_mask);
                *(volatile int*)&g_tok[t] = 0;        // replay-safe reset
            }
        }
        runEq += tot & 0xFFFF;
        runGt += tot >> 16;
    }

    if (tid == 0 && counts_off >= 0)
        out[(size_t)counts_off + e] = (float)total;

    // ---- barrier reset: second ticket round (all blocks past the spin) ----
    __syncthreads();
    if (tid == 0) {
        if (atomicAdd(&g_bar, 1) == 2 * NSEL - 1)
            atomicExch(&g_bar, 0);                    // replay-deterministic
    }
}

// ============================================================================
// Launch: ONE fused kernel (plus a tail memset only for nonstandard layouts).
// ============================================================================
extern "C" void kernel_launch(void* const* d_in, const int* in_sizes, int n_in,
                              void* d_out, int out_size)
{
    const float* inputs = (const float*)d_in[0];  // [8192, 64] f32
    const float* rand   = (const float*)d_in[1];  // [8192, 64] f32
    float* out = (float*)d_out;
    size_t osz = (size_t)out_size;

    // Layout: out = combine_weights [s,e,c] | sec_mask [s,e,c] | exp_counts [e]
    int write_mask = (osz >= 2 * SEC) ? 1 : 0;
    long long counts_off = -1;
    if (osz > SEC && (osz % SEC) == (size_t)E) counts_off = (long long)(osz - E);

    // Zero any bytes past (covered sections + counts) — normally none.
    size_t covered = write_mask ? 2 * SEC : SEC;
    size_t counts_elems = (counts_off >= 0) ? (size_t)E : 0;
    if (osz > covered + counts_elems)
        cudaMemsetAsync((char*)d_out + (covered + counts_elems) * sizeof(float), 0,
                        (osz - covered - counts_elems) * sizeof(float), 0);

    router_fused_kernel<<<NSEL + NFILL, TPB>>>(inputs, rand, out,
                                               write_mask, counts_off);
}

// round 17
// speedup vs baseline: 1.0103x; 1.0103x over previous
#include <cuda_runtime.h>
#include <cuda_bf16.h>
#include <cstdint>
#include <cstddef>

// Problem constants: inputs [8192, 64], capacity = ceil(1.25*8192/64) = 160
#define S   8192
#define E   64
#define CAP 160
#define ROW (E * CAP)               // 10240 floats per token row
#define SEC ((size_t)S * ROW)       // 83,886,080 elements per [s,e,c] section

#define NSEL E                      // 64 select blocks (bids 0..63)
#define FILL_TOK 4                  // token-rows per fill block (both sections)
#define NFILL (S / FILL_TOK)        // 2048 fill blocks
#define TPB 1024
#define NSLOT (E * CAP)             // 10240 compact slots

// -------- device scratch (allocation-free: __device__ globals) --------
__device__ uint8_t  g_expert[S];
__device__ float    g_prob[S];
__device__ unsigned g_rbits[S];
__device__ int      g_bar;          // select-phase barrier
__device__ int      g_lt[NSLOT];    // slot -> token id (-1 = empty slot)
__device__ float    g_lp[NSLOT];    // slot -> combine weight

// ============================================================================
// Block-wide inclusive scan over 1024 ints. *tot = block total.
// ============================================================================
__device__ __forceinline__ int block_incl_scan_1024(int v, int* tot, int* warpsums)
{
    int lane = threadIdx.x & 31, w = threadIdx.x >> 5;
    int inc = v;
    #pragma unroll
    for (int o = 1; o < 32; o <<= 1) {
        int n = __shfl_up_sync(0xFFFFFFFFu, inc, o);
        if (lane >= o) inc += n;
    }
    if (lane == 31) warpsums[w] = inc;
    __syncthreads();
    if (w == 0) {
        int sv = warpsums[lane];
        #pragma unroll
        for (int o = 1; o < 32; o <<= 1) {
            int n = __shfl_up_sync(0xFFFFFFFFu, sv, o);
            if (lane >= o) sv += n;
        }
        warpsums[lane] = sv;
    }
    __syncthreads();
    int res = inc + (w ? warpsums[w - 1] : 0);
    *tot = warpsums[31];
    __syncthreads();
    return res;
}

// ============================================================================
// K1 (fused):
//   bid <  NSEL : token phase (128 tokens) -> co-resident device barrier ->
//                 exact radix select + slot scan -> compact slot table
//                 (g_lt/g_lp) + counts -> exit.
//   bid >= NSEL : PURE zero loop (no fence, no atomics, no checks) -> exit.
// Ordering to the fix-up is provided by the kernel boundary.
// ============================================================================
__global__ void __launch_bounds__(TPB) router_fused_kernel(
    const float* __restrict__ inputs, const float* __restrict__ rand,
    float* __restrict__ out, int write_mask, long long counts_off)
{
    const int bid = blockIdx.x;
    const int tid = threadIdx.x;

    if (bid >= NSEL) {
        // ---------------- fill block: sync-free streaming zero ----------------
        int fid = bid - NSEL;                       // 0 .. NFILL-1
        float4* base  = (float4*)out + (size_t)fid * (FILL_TOK * ROW / 4);
        float4* mbase = base + (SEC / 4);
        const float4 z = make_float4(0.f, 0.f, 0.f, 0.f);
        #pragma unroll
        for (int i = 0; i < FILL_TOK * ROW / 4 / TPB; ++i)   // 10 iterations
            base[tid + TPB * i] = z;
        if (write_mask) {
            #pragma unroll
            for (int i = 0; i < FILL_TOK * ROW / 4 / TPB; ++i)
                mbase[tid + TPB * i] = z;
        }
        return;   // nothing else: no fence, no atomic
    }

    // ------------------- token phase: 128 tokens per block -------------------
    {
        int w    = tid >> 5;
        int lane = tid & 31;
        #pragma unroll
        for (int i = 0; i < 4; ++i) {
            int t = bid * 128 + i * 32 + w;
            float2 v = ((const float2*)(inputs + (size_t)t * E))[lane];
            float m;  int mi;
            if (v.x >= v.y) { m = v.x; mi = 2 * lane; } else { m = v.y; mi = 2 * lane + 1; }
            #pragma unroll
            for (int o = 16; o > 0; o >>= 1) {
                float om  = __shfl_xor_sync(0xFFFFFFFFu, m, o);
                int   omi = __shfl_xor_sync(0xFFFFFFFFu, mi, o);
                if (om > m || (om == m && omi < mi)) { m = om; mi = omi; }
            }
            float s = expf(v.x - m) + expf(v.y - m);
            #pragma unroll
            for (int o = 16; o > 0; o >>= 1)
                s += __shfl_xor_sync(0xFFFFFFFFu, s, o);
            if (lane == 0) {
                g_expert[t] = (uint8_t)mi;
                g_prob[t]   = 1.0f / s;
                g_rbits[t]  = __float_as_uint(rand[(size_t)t * E + mi]);
            }
        }
    }
    // barrier among the 64 select blocks (bids 0..63: all wave-1 co-resident)
    __threadfence();
    __syncthreads();
    if (tid == 0) {
        atomicAdd(&g_bar, 1);
        while (*(volatile int*)&g_bar < NSEL) __nanosleep(64);
    }
    __syncthreads();
    __threadfence();

    // ------------------- radix select + slot scan (expert = bid) -------------
    const int e = bid;
    __shared__ unsigned hist[256];
    __shared__ int s_warpsums[32];
    __shared__ unsigned s_prefix;
    __shared__ int s_k, s_total, s_done_sh;

    if (tid == 0) { s_prefix = 0; s_k = CAP; s_total = 0; s_done_sh = 0; }

    for (int pass = 3; pass >= 0; --pass) {
        __syncthreads();
        if (s_done_sh) break;
        if (tid < 256) hist[tid] = 0;
        __syncthreads();

        unsigned prefix = s_prefix;
        unsigned himask = (pass == 3) ? 0u : (0xFFFFFFFFu << ((pass + 1) * 8));
        int shift = pass * 8;

        #pragma unroll
        for (int c = 0; c < S / TPB; ++c) {
            int t = c * TPB + tid;
            if (g_expert[t] == (uint8_t)e) {
                unsigned b = g_rbits[t];
                if ((b & himask) == (prefix & himask))
                    atomicAdd(&hist[(b >> shift) & 255u], 1u);
            }
        }
        __syncthreads();

        int hv = (tid < 256) ? (int)hist[255 - tid] : 0;
        int tot;
        int suf = block_incl_scan_1024(hv, &tot, s_warpsums);

        int k = s_k;
        __syncthreads();

        if (tid < 256) {
            int i = 255 - tid;
            int above = suf - hv;
            if (pass == 3 && tid == 255) {
                s_total = suf;
                if (suf <= CAP) s_done_sh = 1;
            }
            if (suf >= k && above < k) {
                s_k = k - above;
                s_prefix = prefix | ((unsigned)i << shift);
            }
        }
    }
    __syncthreads();

    const int keep_all = (s_total <= CAP);
    const unsigned T   = s_prefix;
    const int need_eq  = keep_all ? 0 : s_k;
    const int total    = s_total;
    const int kept_cnt = keep_all ? total : CAP;

    int runEq = 0, runGt = 0;
    #pragma unroll
    for (int c = 0; c < S / TPB; ++c) {
        int t = c * TPB + tid;
        bool assigned = (g_expert[t] == (uint8_t)e);
        unsigned b = assigned ? g_rbits[t] : 0u;
        int gtf, eqf;
        if (keep_all) { gtf = assigned ? 1 : 0; eqf = 0; }
        else {
            gtf = (assigned && b >  T) ? 1 : 0;
            eqf = (assigned && b == T) ? 1 : 0;
        }
        int packed = eqf | (gtf << 16);

        int tot;
        int incl = block_incl_scan_1024(packed, &tot, s_warpsums);
        int excl = incl - packed;
        int eq_excl = runEq + (excl & 0xFFFF);
        int gt_excl = runGt + (excl >> 16);

        if (assigned) {
            int kept = gtf || (eqf && eq_excl < need_eq);
            if (kept) {
                int loc = gt_excl + min(eq_excl, need_eq);   // cumsum slot
                g_lt[e * CAP + loc] = t;
                g_lp[e * CAP + loc] = g_prob[t];
            }
        }
        runEq += tot & 0xFFFF;
        runGt += tot >> 16;
    }

    // invalidate unused slots [kept_cnt, CAP)
    for (int c = kept_cnt + tid; c < CAP; c += TPB)
        g_lt[e * CAP + c] = -1;

    if (tid == 0 && counts_off >= 0)
        out[(size_t)counts_off + e] = (float)total;
}

// ============================================================================
// K2 (fix): slot-indexed scatter. idx = e*CAP + c, so the final offset is
// t*ROW + idx — one coalesced load pair, no dependent gather, no division.
// ============================================================================
__global__ void __launch_bounds__(256) router_fix_kernel(
    float* __restrict__ out, int write_mask)
{
    if (blockIdx.x == 0 && threadIdx.x == 0) g_bar = 0;   // replay-safe reset
    int idx = blockIdx.x * 256 + threadIdx.x;             // < NSLOT
    int   t = g_lt[idx];
    float p = g_lp[idx];
    if (t >= 0) {
        size_t off = (size_t)t * ROW + idx;
        out[off] = p;
        if (write_mask) out[SEC + off] = 1.0f;
    }
}

// ============================================================================
// Launch: K1 (fused zero+compute) -> K2 (compact fix-up).
// ============================================================================
extern "C" void kernel_launch(void* const* d_in, const int* in_sizes, int n_in,
                              void* d_out, int out_size)
{
    const float* inputs = (const float*)d_in[0];  // [8192, 64] f32
    const float* rand   = (const float*)d_in[1];  // [8192, 64] f32
    float* out = (float*)d_out;
    size_t osz = (size_t)out_size;

    // Layout: out = combine_weights [s,e,c] | sec_mask [s,e,c] | exp_counts [e]
    int write_mask = (osz >= 2 * SEC) ? 1 : 0;
    long long counts_off = -1;
    if (osz > SEC && (osz % SEC) == (size_t)E) counts_off = (long long)(osz - E);

    // Zero any bytes past (covered sections + counts) — normally none.
    size_t covered = write_mask ? 2 * SEC : SEC;
    size_t counts_elems = (counts_off >= 0) ? (size_t)E : 0;
    if (osz > covered + counts_elems)
        cudaMemsetAsync((char*)d_out + (covered + counts_elems) * sizeof(float), 0,
                        (osz - covered - counts_elems) * sizeof(float), 0);

    router_fused_kernel<<<NSEL + NFILL, TPB>>>(inputs, rand, out,
                                               write_mask, counts_off);
    router_fix_kernel<<<NSLOT / 256, 256>>>(out, write_mask);
}